// round 15
// baseline (speedup 1.0000x reference)
#include <cuda_runtime.h>

#define NQ       12
#define DIM      4096
#define THREADS  256
#define NCLASSES 10
#define NFEAT    36
#define NPAIRS_TOTAL 1024
#define GRID     304            // 2 CTAs/SM x 152 SMs = one resident wave

typedef unsigned long long u64;

struct Cx { float x, y; };
__device__ __forceinline__ Cx cmul(Cx a, Cx b) {
    return Cx{a.x * b.x - a.y * b.y, a.x * b.y + a.y * b.x};
}

// ---- f32x2 helpers ----
__device__ __forceinline__ u64 pk(float lo, float hi) {
    u64 r; asm("mov.b64 %0, {%1,%2};" : "=l"(r) : "f"(lo), "f"(hi)); return r;
}
__device__ __forceinline__ void upk(u64 v, float& lo, float& hi) {
    asm("mov.b64 {%0,%1}, %2;" : "=f"(lo), "=f"(hi) : "l"(v));
}
__device__ __forceinline__ u64 f2fma(u64 a, u64 b, u64 c) {
    u64 r; asm("fma.rn.f32x2 %0, %1, %2, %3;" : "=l"(r) : "l"(a), "l"(b), "l"(c)); return r;
}
__device__ __forceinline__ u64 f2mul(u64 a, u64 b) {
    u64 r; asm("mul.rn.f32x2 %0, %1, %2;" : "=l"(r) : "l"(a), "l"(b)); return r;
}
__device__ __forceinline__ u64 f2add(u64 a, u64 b) {
    u64 r; asm("add.rn.f32x2 %0, %1, %2;" : "=l"(r) : "l"(a), "l"(b)); return r;
}
__device__ __forceinline__ u64 f2sub(u64 a, u64 b) {
    u64 r; asm("sub.rn.f32x2 %0, %1, %2;" : "=l"(r) : "l"(a), "l"(b)); return r;
}
__device__ __forceinline__ u64 splat(float x) { return pk(x, x); }

// ---- addressing ----
__device__ __forceinline__ int swzc(int i) { return i ^ ((i >> 5) & 31); }

template<int S0,int S1,int S2,int S3>
__device__ __forceinline__ int offj(int j) {
    return ((j & 1) << S0) | (((j >> 1) & 1) << S1) | (((j >> 2) & 1) << S2) | (((j >> 3) & 1) << S3);
}
template<int L0,int L1,int L2,int L3,int L4,int W0,int W1,int W2>
__device__ __forceinline__ int mkbase(int t) {
    return ((t & 1) << L0) | (((t >> 1) & 1) << L1) | (((t >> 2) & 1) << L2) |
           (((t >> 3) & 1) << L3) | (((t >> 4) & 1) << L4) |
           (((t >> 5) & 1) << W0) | (((t >> 6) & 1) << W1) | (((t >> 7) & 1) << W2);
}

// SMEM element: one amplitude = {R u64, I u64} (16 bytes) -> LDS.128/STS.128.
template<int S0,int S1,int S2,int S3>
__device__ __forceinline__ void vld(u64 R[16], u64 I[16], const longlong2* cxp, int pb) {
#pragma unroll
    for (int j = 0; j < 16; j++) {
        const int ad = pb ^ swzc(offj<S0,S1,S2,S3>(j));
        const longlong2 v = cxp[ad];
        R[j] = (u64)v.x; I[j] = (u64)v.y;
    }
}
template<int S0,int S1,int S2,int S3>
__device__ __forceinline__ void vst(const u64 R[16], const u64 I[16], longlong2* cxp, int pb) {
#pragma unroll
    for (int j = 0; j < 16; j++) {
        const int ad = pb ^ swzc(offj<S0,S1,S2,S3>(j));
        cxp[ad] = make_longlong2((long long)R[j], (long long)I[j]);
    }
}

// ---- coefficient vector loads (LDS.128) ----
#define LOAD_G7(g)                                                  \
    const longlong2* Gv = reinterpret_cast<const longlong2*>(g);    \
    const longlong2 G01 = Gv[0], G23 = Gv[1], G45 = Gv[2], G67 = Gv[3]; \
    const u64 g0 = (u64)G01.x, g1 = (u64)G01.y, g2 = (u64)G23.x,    \
              g3 = (u64)G23.y, g4 = (u64)G45.x, g5 = (u64)G45.y,    \
              g6 = (u64)G67.x; (void)g5;

// ---- gates ----
// SU(2): U = [[u00,u01],[-u01*,u00*]]
// GS: [0]=u00x [1]=u01x [2]=u00y [3]=u01y [4]=-u00y [5]=-u01y [6]=-u01x
#define V1Q_BODY(jlo, jhi) do {                                                  \
    const u64 a = R[jlo], ai = I[jlo], b = R[jhi], bi = I[jhi];                  \
    R[jlo] = f2fma(g0, a, f2fma(g4, ai, f2fma(g1, b, f2mul(g5, bi))));           \
    I[jlo] = f2fma(g2, a, f2fma(g0, ai, f2fma(g3, b, f2mul(g1, bi))));           \
    R[jhi] = f2fma(g6, a, f2fma(g5, ai, f2fma(g0, b, f2mul(g2, bi))));           \
    I[jhi] = f2fma(g3, a, f2fma(g6, ai, f2fma(g4, b, f2mul(g0, bi))));           \
} while (0)

template<int K>
__device__ __forceinline__ void v1q(u64 R[16], u64 I[16], const u64* g) {
    LOAD_G7(g)
#pragma unroll
    for (int j = 0; j < 16; j++) {
        if (!((j >> K) & 1)) { const int j1 = j | (1 << K); V1Q_BODY(j, j1); }
    }
}
template<int K>  // first gate on purely real state (I == 0)
__device__ __forceinline__ void v1q_real(u64 R[16], u64 I[16], const u64* g) {
    LOAD_G7(g)
#pragma unroll
    for (int j = 0; j < 16; j++) {
        if (!((j >> K) & 1)) {
            const int j1 = j | (1 << K);
            const u64 a = R[j], b = R[j1];
            R[j]  = f2fma(g0, a, f2mul(g1, b));
            I[j]  = f2fma(g2, a, f2mul(g3, b));
            R[j1] = f2fma(g6, a, f2mul(g0, b));
            I[j1] = f2fma(g3, a, f2mul(g4, b));
        }
    }
}
// Controlled-1q (fusion of 1q(tgt) then CRX(ctrl,tgt)): ctrl bit KC, tgt bit KT.
template<int KC,int KT>
__device__ __forceinline__ void c1q(u64 R[16], u64 I[16], const u64* gu, const u64* gv) {
    {
        LOAD_G7(gu)
#pragma unroll
        for (int j = 0; j < 16; j++)
            if (!((j >> KT) & 1) && !((j >> KC) & 1)) { const int j1 = j | (1 << KT); V1Q_BODY(j, j1); }
    }
    {
        LOAD_G7(gv)
#pragma unroll
        for (int j = 0; j < 16; j++)
            if (!((j >> KT) & 1) && ((j >> KC) & 1)) { const int j1 = j | (1 << KT); V1Q_BODY(j, j1); }
    }
}
// CRX: q[0]={c,c} q[1]={s,s} q[2]={-s,-s}  (CC rows padded to 4 u64, 32B-aligned)
template<int KC,int KT>
__device__ __forceinline__ void vcrx(u64 R[16], u64 I[16], const u64* q) {
    const longlong2 Q01 = *reinterpret_cast<const longlong2*>(q);
    const u64 q0 = (u64)Q01.x, q1 = (u64)Q01.y, q2 = q[2];
#pragma unroll
    for (int j = 0; j < 16; j++) {
        if (((j >> KC) & 1) && !((j >> KT) & 1)) {
            const int j1 = j | (1 << KT);
            const u64 a = R[j], ai = I[j], b = R[j1], bi = I[j1];
            R[j]  = f2fma(q0, a,  f2mul(q1, bi));
            I[j]  = f2fma(q0, ai, f2mul(q2, b));
            R[j1] = f2fma(q0, b,  f2mul(q1, ai));
            I[j1] = f2fma(q0, bi, f2mul(q2, a));
        }
    }
}

// ---- reductions ----
__device__ __forceinline__ void red2w4(u64 v, u64* fw4, int feat) {
    v = f2add(v, __shfl_xor_sync(0xffffffffu, v, 16));
    v = f2add(v, __shfl_xor_sync(0xffffffffu, v, 8));
    v = f2add(v, __shfl_xor_sync(0xffffffffu, v, 4));
    const int lane = threadIdx.x & 31;
    if (lane < 4) fw4[lane * NFEAT + feat] = v;
}

struct XY { u64 cr, cp, cn; };
template<int K>
__device__ __forceinline__ XY vcross_acc(const u64 R[16], const u64 I[16]) {
    u64 cr = 0ull, cp = 0ull, cn = 0ull;
#pragma unroll
    for (int j = 0; j < 16; j++) {
        if (!((j >> K) & 1)) {
            const int j1 = j | (1 << K);
            cr = f2fma(R[j], R[j1], f2fma(I[j], I[j1], cr));
            cp = f2fma(R[j], I[j1], cp);
            cn = f2fma(I[j], R[j1], cn);
        }
    }
    return XY{cr, cp, cn};
}
__device__ __forceinline__ void vcross_fin(XY a, u64* fw4, int q) {
    red2w4(f2add(a.cr, a.cr), fw4, q);
    const u64 ci = f2sub(a.cp, a.cn);
    red2w4(f2add(ci, ci), fw4, NQ + q);
}

// Fused-1q matrix U for (layer, wire).
__device__ __forceinline__ void fused_u(const float* angles, int layer, int wire, Cx& u00, Cx& u01) {
    const int base = layer * 48;
    const float tx = angles[base + wire];
    const float ty = angles[base + 12 + wire];
    const float tz = angles[base + 24 + wire];
    const float cxv = cosf(0.5f*tx), sxv = sinf(0.5f*tx);
    const float cyv = cosf(0.5f*ty), syv = sinf(0.5f*ty);
    const float czv = cosf(0.5f*tz), szv = sinf(0.5f*tz);
    Cx m00{cyv*cxv,  syv*sxv};
    Cx m01{-syv*cxv, -cyv*sxv};
    Cx ezm{czv, -szv};
    u00 = cmul(ezm, m00);
    u01 = cmul(ezm, m01);
}
// V = RX(theta) * U
__device__ __forceinline__ void rx_compose(Cx u00, Cx u01, float c, float s, Cx& v00, Cx& v01) {
    v00 = Cx{c*u00.x + s*u01.y, c*u00.y + s*u01.x};
    v01 = Cx{c*u01.x - s*u00.y, c*u01.y - s*u00.x};
}

__global__ __launch_bounds__(THREADS, 2)
void qsim_kernel(const float* __restrict__ sv,
                 const float* __restrict__ angles,
                 const float* __restrict__ Wm,
                 const float* __restrict__ bv,
                 float* __restrict__ out)
{
    extern __shared__ longlong2 cxp[];      // cxp[DIM] = {R,I} packed pairs, 64 KB

    __shared__ u64 GS[24][8];     // SU(2)-compressed fused 1q coefs
    __shared__ u64 FGS[12][8];    // fused V = RX(crx)*U coefs (ctrl=1 branches)
    __shared__ u64 CC[24][4];     // CRX coefs, padded to 32B rows
    __shared__ u64 FW[32][NFEAT]; // 4 partials per warp, packed 2 batches
    __shared__ u64 FZ[NFEAT];     // reduced features

    const int tid  = threadIdx.x;
    const int bidx = blockIdx.x;
    const int warp = tid >> 5;
    u64* fw4 = &FW[warp * 4][0];

    u64 R[16], I[16];

    int pair = bidx;

    // ---- Prologue: issue first pair's LDGs; latency hides under coef setup ----
    {
        const float* in0 = sv + ((size_t)(2 * pair))     * DIM;
        const float* in1 = sv + ((size_t)(2 * pair) + 1) * DIM;
#pragma unroll
        for (int j = 0; j < 16; j++) {
            const int idx = (j << 8) | tid;
            R[j] = pk(in0[idx], in1[idx]);
            I[j] = 0ull;
        }
    }

    // ---- Coefficient setup (ONCE per CTA — shared across all its pairs) ----
    if (tid < 24) {
        const int layer = tid / NQ;
        const int wire  = tid % NQ;
        Cx u00, u01;
        fused_u(angles, layer, wire, u00, u01);
        GS[tid][0] = splat(u00.x);  GS[tid][1] = splat(u01.x);
        GS[tid][2] = splat(u00.y);  GS[tid][3] = splat(u01.y);
        GS[tid][4] = splat(-u00.y); GS[tid][5] = splat(-u01.y);
        GS[tid][6] = splat(-u01.x); GS[tid][7] = 0ull;
        const float tc = angles[layer * 48 + 36 + wire];
        const float c = cosf(0.5f*tc), s = sinf(0.5f*tc);
        CC[tid][0] = pk(c, c); CC[tid][1] = pk(s, s); CC[tid][2] = pk(-s, -s); CC[tid][3] = 0ull;
    } else if (tid >= 32 && tid < 44) {
        const int f = tid - 32;
        const int layer = (f == 11) ? 1 : 0;
        const int wire  = (f == 11) ? 0 : (f + 1);
        const float th  = (f == 11) ? angles[84] : angles[36 + f];
        Cx u00, u01, v00, v01;
        fused_u(angles, layer, wire, u00, u01);
        rx_compose(u00, u01, cosf(0.5f*th), sinf(0.5f*th), v00, v01);
        FGS[f][0] = splat(v00.x);  FGS[f][1] = splat(v01.x);
        FGS[f][2] = splat(v00.y);  FGS[f][3] = splat(v01.y);
        FGS[f][4] = splat(-v00.y); FGS[f][5] = splat(-v01.y);
        FGS[f][6] = splat(-v01.x); FGS[f][7] = 0ull;
    }
    // Zero only the WHT feature columns (28..35) — the rest are fully written.
    {
        const int row = tid >> 3, col = 28 + (tid & 7);
        FW[row][col] = 0ull;
    }
    __syncthreads();

    for (;;) {
        // ---- P1: S={8,9,10,11} (b0=w3,b1=w2,b2=w1,b3=w0) ----
        {
            v1q_real<3>(R, I, GS[0]);        // 1q w0 (bit11), state real
            c1q<3,2>(R, I, GS[1], FGS[0]);   // 1q w1 + CRX(0,1)
            c1q<2,1>(R, I, GS[2], FGS[1]);   // 1q w2 + CRX(1,2)
            c1q<1,0>(R, I, GS[3], FGS[2]);   // 1q w3 + CRX(2,3)
            vst<8,9,10,11>(R, I, cxp, swzc(tid));
        }
        __syncthreads();

        // ---- P2: S={5,6,7,8} ----
        {
            const int pb = swzc(mkbase<0,1,2,3,4, 9,10,11>(tid));
            vld<5,6,7,8>(R, I, cxp, pb);
            c1q<3,2>(R, I, GS[4], FGS[3]);   // 1q w4 + CRX(3,4)
            c1q<2,1>(R, I, GS[5], FGS[4]);   // 1q w5 + CRX(4,5)
            c1q<1,0>(R, I, GS[6], FGS[5]);   // 1q w6 + CRX(5,6)
            vst<5,6,7,8>(R, I, cxp, pb);
        }
        __syncthreads();

        // ---- P3: S={2,3,4,5} ----
        {
            const int pb = swzc(mkbase<0,1,7,8,9, 6,10,11>(tid));
            vld<2,3,4,5>(R, I, cxp, pb);
            c1q<3,2>(R, I, GS[7], FGS[6]);   // 1q w7 + CRX(6,7)
            c1q<2,1>(R, I, GS[8], FGS[7]);   // 1q w8 + CRX(7,8)
            c1q<1,0>(R, I, GS[9], FGS[8]);   // 1q w9 + CRX(8,9)
            vst<2,3,4,5>(R, I, cxp, pb);
        }
        __syncthreads();

        XY a11, a10;     // deferred from P4
        // ---- P4 (mega): S={0,1,2,11} ----
        {
            const int pb = swzc(mkbase<5,6,7,3,4, 8,9,10>(tid));
            vld<0,1,2,11>(R, I, cxp, pb);
            c1q<2,1>(R, I, GS[10], FGS[9]);  // L0 1q w10 + CRX(9,10)
            c1q<1,0>(R, I, GS[11], FGS[10]); // L0 1q w11 + CRX(10,11)
            vcrx<0,3>(R, I, CC[11]);         // L0 CRX(11,0)
            v1q<0>(R, I, GS[23]);            // L1 1q w11
            v1q<1>(R, I, GS[22]);            // L1 1q w10
            v1q<2>(R, I, GS[21]);            // L1 1q w9
            c1q<0,3>(R, I, GS[12], FGS[11]); // L1 1q w0 + L1 CRX(11,0)
            vcrx<1,0>(R, I, CC[13]);         // L1 CRX(10,11)
            vcrx<2,1>(R, I, CC[14]);         // L1 CRX(9,10)
            vst<0,1,2,11>(R, I, cxp, pb);
            a11 = vcross_acc<0>(R, I);       // idx bit0 -> qubit 11 (final)
            a10 = vcross_acc<1>(R, I);       // idx bit1 -> qubit 10 (final)
        }
        __syncthreads();

        XY a9, a8, a7;   // deferred from P5
        // ---- P5: S={2,3,4,5}; fin(P4) in load shadow ----
        {
            const int pb = swzc(mkbase<0,1,7,8,9, 6,10,11>(tid));
            vld<2,3,4,5>(R, I, cxp, pb);
            vcross_fin(a11, fw4, 11);
            vcross_fin(a10, fw4, 10);
            v1q<1>(R, I, GS[20]);
            v1q<2>(R, I, GS[19]);
            v1q<3>(R, I, GS[18]);
            vcrx<1,0>(R, I, CC[15]);    // CRX(8,9)
            vcrx<2,1>(R, I, CC[16]);    // CRX(7,8)
            vcrx<3,2>(R, I, CC[17]);    // CRX(6,7)
            vst<2,3,4,5>(R, I, cxp, pb);
            a9 = vcross_acc<0>(R, I);
            a8 = vcross_acc<1>(R, I);
            a7 = vcross_acc<2>(R, I);
        }
        __syncthreads();

        XY a6, a5, a4;   // deferred from P6
        // ---- P6: S={5,6,7,8}; fin(P5) in load shadow ----
        {
            const int pb = swzc(mkbase<0,1,2,3,4, 9,10,11>(tid));
            vld<5,6,7,8>(R, I, cxp, pb);
            vcross_fin(a9, fw4, 9);
            vcross_fin(a8, fw4, 8);
            vcross_fin(a7, fw4, 7);
            v1q<1>(R, I, GS[17]);
            v1q<2>(R, I, GS[16]);
            v1q<3>(R, I, GS[15]);
            vcrx<1,0>(R, I, CC[18]);    // CRX(5,6)
            vcrx<2,1>(R, I, CC[19]);    // CRX(4,5)
            vcrx<3,2>(R, I, CC[20]);    // CRX(3,4)
            vst<5,6,7,8>(R, I, cxp, pb);
            a6 = vcross_acc<0>(R, I);
            a5 = vcross_acc<1>(R, I);
            a4 = vcross_acc<2>(R, I);
        }
        __syncthreads();

        // ---- P7: S={8,9,10,11}; fin(P6) in load shadow; all Z + X/Y q3..q0. NO store. ----
        {
            const int pb = swzc(tid);
            vld<8,9,10,11>(R, I, cxp, pb);
            vcross_fin(a6, fw4, 6);
            vcross_fin(a5, fw4, 5);
            vcross_fin(a4, fw4, 4);
            v1q<1>(R, I, GS[14]);       // wire2
            v1q<2>(R, I, GS[13]);       // wire1
            vcrx<1,0>(R, I, CC[21]);    // CRX(2,3)
            vcrx<2,1>(R, I, CC[22]);    // CRX(1,2)
            vcrx<3,2>(R, I, CC[23]);    // CRX(0,1)

            // |amp|^2 sums (packed per batch)
            u64 tot2 = 0ull, d0v = 0ull, d1v = 0ull, d2v = 0ull, d3v = 0ull;
#pragma unroll
            for (int j = 0; j < 16; j++) {
                const u64 p2 = f2fma(R[j], R[j], f2mul(I[j], I[j]));
                tot2 = f2add(tot2, p2);
                if (j & 1) d0v = f2add(d0v, p2);
                if (j & 2) d1v = f2add(d1v, p2);
                if (j & 4) d2v = f2add(d2v, p2);
                if (j & 8) d3v = f2add(d3v, p2);
            }
            // Z for tile bits 8..11 -> qubits 3..0
            red2w4(f2sub(tot2, f2add(d0v, d0v)), fw4, 24 + 3);
            red2w4(f2sub(tot2, f2add(d1v, d1v)), fw4, 24 + 2);
            red2w4(f2sub(tot2, f2add(d2v, d2v)), fw4, 24 + 1);
            red2w4(f2sub(tot2, f2add(d3v, d3v)), fw4, 24 + 0);

            // Z for free bits: 5-stage Walsh-Hadamard butterfly over the warp.
            {
                u64 x = tot2;
#pragma unroll
                for (int m = 1; m <= 16; m <<= 1) {
                    const u64 y = __shfl_xor_sync(0xffffffffu, x, m);
                    x = (tid & m) ? f2sub(y, x) : f2add(x, y);
                }
                const int lane = tid & 31;
                if (lane == 1)  fw4[24 + 11] = x;   // fb0 -> q11
                if (lane == 2)  fw4[24 + 10] = x;   // fb1 -> q10
                if (lane == 4)  fw4[24 + 9]  = x;   // fb2 -> q9
                if (lane == 8)  fw4[24 + 8]  = x;   // fb3 -> q8
                if (lane == 16) fw4[24 + 7]  = x;   // fb4 -> q7
                if (lane == 0) {
#pragma unroll
                    for (int fb = 5; fb < 8; fb++) {   // warp-uniform sign bits -> q6,q5,q4
                        const u64 v = ((tid >> fb) & 1) ? f2sub(0ull, x) : x;
                        fw4[24 + (11 - fb)] = v;
                    }
                }
            }

            // X/Y for tile bits 8..11 -> qubits 3..0 (terminal: inline)
            vcross_fin(vcross_acc<0>(R, I), fw4, 3);
            vcross_fin(vcross_acc<1>(R, I), fw4, 2);
            vcross_fin(vcross_acc<2>(R, I), fw4, 1);
            vcross_fin(vcross_acc<3>(R, I), fw4, 0);
        }

        // ---- Prefetch next pair's state into now-dead R/I (hides LDG under reduce) ----
        const int next = pair + GRID;
        const bool more = (next < NPAIRS_TOTAL);
        if (more) {
            const float* in0 = sv + ((size_t)(2 * next))     * DIM;
            const float* in1 = sv + ((size_t)(2 * next) + 1) * DIM;
#pragma unroll
            for (int j = 0; j < 16; j++) {
                const int idx = (j << 8) | tid;
                R[j] = pk(in0[idx], in1[idx]);
                I[j] = 0ull;
            }
        }
        __syncthreads();

        // ---- Parallel reduce: 32 rows -> 8 rows, then 8 -> 1 ----
        if (tid < 8 * NFEAT) {                   // (only tid<256 exist; cols 32-35
            const int feat = tid / 8;            //  are WHT cols: base rows only, OK)
            const int grp  = tid % 8;
            const int r0 = grp * 4;
            u64 acc = f2add(f2add(FW[r0][feat], FW[r0+1][feat]),
                            f2add(FW[r0+2][feat], FW[r0+3][feat]));
            FW[r0][feat] = acc;
        }
        __syncthreads();
        if (tid < NFEAT) {
            u64 acc = FW[0][tid];
#pragma unroll
            for (int g = 1; g < 8; g++) acc = f2add(acc, FW[g * 4][tid]);
            FZ[tid] = acc;
        }
        __syncthreads();

        // ---- Head + FW re-zero for next pair ----
        if (tid < 2 * NCLASSES) {
            const int batch = tid / NCLASSES;
            const int c     = tid % NCLASSES;
            const float* fz = (const float*)FZ;     // {b0,b1} interleaved per feature
            float acc = bv[c];
#pragma unroll
            for (int j = 0; j < NFEAT; ++j)
                acc += Wm[c * NFEAT + j] * fz[2 * j + batch];
            out[((size_t)(2 * pair) + batch) * NCLASSES + c] = acc;
        }
        {
            const int row = tid >> 3, col = 28 + (tid & 7);
            FW[row][col] = 0ull;
        }

        if (!more) return;
        pair = next;
        __syncthreads();   // FW zero + FZ read complete before next pair's writes
    }
}

extern "C" void kernel_launch(void* const* d_in, const int* in_sizes, int n_in,
                              void* d_out, int out_size)
{
    const float* sv     = (const float*)d_in[0];  // [2048, 4096]
    const float* angles = (const float*)d_in[1];  // [96]
    const float* Wm     = (const float*)d_in[2];  // [10, 36]
    const float* bv     = (const float*)d_in[3];  // [10]
    float* out          = (float*)d_out;          // [2048, 10]
    (void)in_sizes; (void)n_in; (void)out_size;

    const int smem_bytes = DIM * (int)sizeof(longlong2);  // 64 KB dynamic
    cudaFuncSetAttribute(qsim_kernel, cudaFuncAttributeMaxDynamicSharedMemorySize, smem_bytes);
    qsim_kernel<<<GRID, THREADS, smem_bytes>>>(sv, angles, Wm, bv, out);
}

// round 17
// speedup vs baseline: 1.0408x; 1.0408x over previous
#include <cuda_runtime.h>

#define NQ       12
#define DIM      4096
#define THREADS  256
#define NCLASSES 10
#define NFEAT    36

typedef unsigned long long u64;

struct Cx { float x, y; };
__device__ __forceinline__ Cx cmul(Cx a, Cx b) {
    return Cx{a.x * b.x - a.y * b.y, a.x * b.y + a.y * b.x};
}

// ---- f32x2 helpers ----
__device__ __forceinline__ u64 pk(float lo, float hi) {
    u64 r; asm("mov.b64 %0, {%1,%2};" : "=l"(r) : "f"(lo), "f"(hi)); return r;
}
__device__ __forceinline__ void upk(u64 v, float& lo, float& hi) {
    asm("mov.b64 {%0,%1}, %2;" : "=f"(lo), "=f"(hi) : "l"(v));
}
__device__ __forceinline__ u64 f2fma(u64 a, u64 b, u64 c) {
    u64 r; asm("fma.rn.f32x2 %0, %1, %2, %3;" : "=l"(r) : "l"(a), "l"(b), "l"(c)); return r;
}
__device__ __forceinline__ u64 f2mul(u64 a, u64 b) {
    u64 r; asm("mul.rn.f32x2 %0, %1, %2;" : "=l"(r) : "l"(a), "l"(b)); return r;
}
__device__ __forceinline__ u64 f2add(u64 a, u64 b) {
    u64 r; asm("add.rn.f32x2 %0, %1, %2;" : "=l"(r) : "l"(a), "l"(b)); return r;
}
__device__ __forceinline__ u64 f2sub(u64 a, u64 b) {
    u64 r; asm("sub.rn.f32x2 %0, %1, %2;" : "=l"(r) : "l"(a), "l"(b)); return r;
}
__device__ __forceinline__ u64 splat(float x) { return pk(x, x); }

// ---- addressing ----
__device__ __forceinline__ int swzc(int i) { return i ^ ((i >> 5) & 31); }

template<int S0,int S1,int S2,int S3>
__device__ __forceinline__ int offj(int j) {
    return ((j & 1) << S0) | (((j >> 1) & 1) << S1) | (((j >> 2) & 1) << S2) | (((j >> 3) & 1) << S3);
}
template<int L0,int L1,int L2,int L3,int L4,int W0,int W1,int W2>
__device__ __forceinline__ int mkbase(int t) {
    return ((t & 1) << L0) | (((t >> 1) & 1) << L1) | (((t >> 2) & 1) << L2) |
           (((t >> 3) & 1) << L3) | (((t >> 4) & 1) << L4) |
           (((t >> 5) & 1) << W0) | (((t >> 6) & 1) << W1) | (((t >> 7) & 1) << W2);
}

// Single-amplitude SMEM load (LDS.128) — used for interleaved load/compute.
template<int S0,int S1,int S2,int S3>
__device__ __forceinline__ void ldj(u64 R[16], u64 I[16], const longlong2* cxp, int pb, int j) {
    const int ad = pb ^ swzc(offj<S0,S1,S2,S3>(j));
    const longlong2 v = cxp[ad];
    R[j] = (u64)v.x; I[j] = (u64)v.y;
}
template<int S0,int S1,int S2,int S3>
__device__ __forceinline__ void vst(const u64 R[16], const u64 I[16], longlong2* cxp, int pb) {
#pragma unroll
    for (int j = 0; j < 16; j++) {
        const int ad = pb ^ swzc(offj<S0,S1,S2,S3>(j));
        cxp[ad] = make_longlong2((long long)R[j], (long long)I[j]);
    }
}

// ---- coefficient vector loads (LDS.128) ----
#define LOAD_G7(g)                                                  \
    const longlong2* Gv = reinterpret_cast<const longlong2*>(g);    \
    const longlong2 G01 = Gv[0], G23 = Gv[1], G45 = Gv[2], G67 = Gv[3]; \
    const u64 g0 = (u64)G01.x, g1 = (u64)G01.y, g2 = (u64)G23.x,    \
              g3 = (u64)G23.y, g4 = (u64)G45.x, g5 = (u64)G45.y,    \
              g6 = (u64)G67.x; (void)g5;

// ---- gates ----
// SU(2): U = [[u00,u01],[-u01*,u00*]]
// GS: [0]=u00x [1]=u01x [2]=u00y [3]=u01y [4]=-u00y [5]=-u01y [6]=-u01x
#define V1Q_BODY(jlo, jhi) do {                                                  \
    const u64 a = R[jlo], ai = I[jlo], b = R[jhi], bi = I[jhi];                  \
    R[jlo] = f2fma(g0, a, f2fma(g4, ai, f2fma(g1, b, f2mul(g5, bi))));           \
    I[jlo] = f2fma(g2, a, f2fma(g0, ai, f2fma(g3, b, f2mul(g1, bi))));           \
    R[jhi] = f2fma(g6, a, f2fma(g5, ai, f2fma(g0, b, f2mul(g2, bi))));           \
    I[jhi] = f2fma(g3, a, f2fma(g6, ai, f2fma(g4, b, f2mul(g0, bi))));           \
} while (0)

#define LD4(j0,j1,j2,j3)                         \
    ldj<S0,S1,S2,S3>(R, I, cxp, pb, j0);         \
    ldj<S0,S1,S2,S3>(R, I, cxp, pb, j1);         \
    ldj<S0,S1,S2,S3>(R, I, cxp, pb, j2);         \
    ldj<S0,S1,S2,S3>(R, I, cxp, pb, j3);

template<int K>
__device__ __forceinline__ void v1q(u64 R[16], u64 I[16], const u64* g) {
    LOAD_G7(g)
#pragma unroll
    for (int j = 0; j < 16; j++) {
        if (!((j >> K) & 1)) { const int j1 = j | (1 << K); V1Q_BODY(j, j1); }
    }
}
template<int K>  // first gate on purely real state (I == 0)
__device__ __forceinline__ void v1q_real(u64 R[16], u64 I[16], const u64* g) {
    LOAD_G7(g)
#pragma unroll
    for (int j = 0; j < 16; j++) {
        if (!((j >> K) & 1)) {
            const int j1 = j | (1 << K);
            const u64 a = R[j], b = R[j1];
            R[j]  = f2fma(g0, a, f2mul(g1, b));
            I[j]  = f2fma(g2, a, f2mul(g3, b));
            R[j1] = f2fma(g6, a, f2mul(g0, b));
            I[j1] = f2fma(g3, a, f2mul(g4, b));
        }
    }
}
// Controlled-1q (fusion of 1q(tgt) then CRX(ctrl,tgt)): ctrl bit KC, tgt bit KT.
template<int KC,int KT>
__device__ __forceinline__ void c1q(u64 R[16], u64 I[16], const u64* gu, const u64* gv) {
    {
        LOAD_G7(gu)
#pragma unroll
        for (int j = 0; j < 16; j++)
            if (!((j >> KT) & 1) && !((j >> KC) & 1)) { const int j1 = j | (1 << KT); V1Q_BODY(j, j1); }
    }
    {
        LOAD_G7(gv)
#pragma unroll
        for (int j = 0; j < 16; j++)
            if (!((j >> KT) & 1) && ((j >> KC) & 1)) { const int j1 = j | (1 << KT); V1Q_BODY(j, j1); }
    }
}
// CRX: q[0]={c,c} q[1]={s,s} q[2]={-s,-s}
template<int KC,int KT>
__device__ __forceinline__ void vcrx(u64 R[16], u64 I[16], const u64* q) {
    const longlong2 Q01 = *reinterpret_cast<const longlong2*>(q);
    const u64 q0 = (u64)Q01.x, q1 = (u64)Q01.y, q2 = q[2];
#pragma unroll
    for (int j = 0; j < 16; j++) {
        if (((j >> KC) & 1) && !((j >> KT) & 1)) {
            const int j1 = j | (1 << KT);
            const u64 a = R[j], ai = I[j], b = R[j1], bi = I[j1];
            R[j]  = f2fma(q0, a,  f2mul(q1, bi));
            I[j]  = f2fma(q0, ai, f2mul(q2, b));
            R[j1] = f2fma(q0, b,  f2mul(q1, ai));
            I[j1] = f2fma(q0, bi, f2mul(q2, a));
        }
    }
}

// ---- reductions ----
__device__ __forceinline__ void red2w4(u64 v, u64* fw4, int feat) {
    v = f2add(v, __shfl_xor_sync(0xffffffffu, v, 16));
    v = f2add(v, __shfl_xor_sync(0xffffffffu, v, 8));
    v = f2add(v, __shfl_xor_sync(0xffffffffu, v, 4));
    const int lane = threadIdx.x & 31;
    if (lane < 4) fw4[lane * NFEAT + feat] = v;
}

struct XY { u64 cr, cp, cn; };
template<int K>
__device__ __forceinline__ XY vcross_acc(const u64 R[16], const u64 I[16]) {
    u64 cr = 0ull, cp = 0ull, cn = 0ull;
#pragma unroll
    for (int j = 0; j < 16; j++) {
        if (!((j >> K) & 1)) {
            const int j1 = j | (1 << K);
            cr = f2fma(R[j], R[j1], f2fma(I[j], I[j1], cr));
            cp = f2fma(R[j], I[j1], cp);
            cn = f2fma(I[j], R[j1], cn);
        }
    }
    return XY{cr, cp, cn};
}
__device__ __forceinline__ void vcross_fin(XY a, u64* fw4, int q) {
    red2w4(f2add(a.cr, a.cr), fw4, q);
    const u64 ci = f2sub(a.cp, a.cn);
    red2w4(f2add(ci, ci), fw4, NQ + q);
}

// Fused-1q matrix U for (layer, wire).
__device__ __forceinline__ void fused_u(const float* angles, int layer, int wire, Cx& u00, Cx& u01) {
    const int base = layer * 48;
    const float tx = angles[base + wire];
    const float ty = angles[base + 12 + wire];
    const float tz = angles[base + 24 + wire];
    const float cxv = cosf(0.5f*tx), sxv = sinf(0.5f*tx);
    const float cyv = cosf(0.5f*ty), syv = sinf(0.5f*ty);
    const float czv = cosf(0.5f*tz), szv = sinf(0.5f*tz);
    Cx m00{cyv*cxv,  syv*sxv};
    Cx m01{-syv*cxv, -cyv*sxv};
    Cx ezm{czv, -szv};
    u00 = cmul(ezm, m00);
    u01 = cmul(ezm, m01);
}
// V = RX(theta) * U
__device__ __forceinline__ void rx_compose(Cx u00, Cx u01, float c, float s, Cx& v00, Cx& v01) {
    v00 = Cx{c*u00.x + s*u01.y, c*u00.y + s*u01.x};
    v01 = Cx{c*u01.x - s*u00.y, c*u01.y - s*u00.x};
}

__global__ __launch_bounds__(THREADS, 2)
void qsim_kernel(const float* __restrict__ sv,
                 const float* __restrict__ angles,
                 const float* __restrict__ Wm,
                 const float* __restrict__ bv,
                 float* __restrict__ out)
{
    extern __shared__ longlong2 cxp[];      // cxp[DIM] = {R,I} packed pairs, 64 KB

    __shared__ u64 GS[24][8];     // SU(2)-compressed fused 1q coefs
    __shared__ u64 FGS[12][8];    // fused V = RX(crx)*U coefs (ctrl=1 branches)
    __shared__ u64 CC[24][4];     // CRX coefs, padded to 32B rows
    __shared__ u64 FW[32][NFEAT]; // 4 partials per warp, packed 2 batches
    __shared__ u64 FZ[NFEAT];     // reduced features

    const int tid  = threadIdx.x;
    const int bidx = blockIdx.x;
    const int warp = tid >> 5;
    u64* fw4 = &FW[warp * 4][0];

    u64 R[16], I[16];

    // ---- Hoisted gmem load: issue LDGs first; latency hides under coef setup ----
    {
        const float* in0 = sv + ((size_t)(2 * bidx))     * DIM;
        const float* in1 = sv + ((size_t)(2 * bidx) + 1) * DIM;
#pragma unroll
        for (int j = 0; j < 16; j++) {
            const int idx = (j << 8) | tid;
            R[j] = pk(in0[idx], in1[idx]);
            I[j] = 0ull;
        }
    }

    // ---- Coefficient setup ----
    if (tid < 24) {
        const int layer = tid / NQ;
        const int wire  = tid % NQ;
        Cx u00, u01;
        fused_u(angles, layer, wire, u00, u01);
        GS[tid][0] = splat(u00.x);  GS[tid][1] = splat(u01.x);
        GS[tid][2] = splat(u00.y);  GS[tid][3] = splat(u01.y);
        GS[tid][4] = splat(-u00.y); GS[tid][5] = splat(-u01.y);
        GS[tid][6] = splat(-u01.x); GS[tid][7] = 0ull;
        const float tc = angles[layer * 48 + 36 + wire];
        const float c = cosf(0.5f*tc), s = sinf(0.5f*tc);
        CC[tid][0] = pk(c, c); CC[tid][1] = pk(s, s); CC[tid][2] = pk(-s, -s); CC[tid][3] = 0ull;
    } else if (tid >= 32 && tid < 44) {
        const int f = tid - 32;
        const int layer = (f == 11) ? 1 : 0;
        const int wire  = (f == 11) ? 0 : (f + 1);
        const float th  = (f == 11) ? angles[84] : angles[36 + f];
        Cx u00, u01, v00, v01;
        fused_u(angles, layer, wire, u00, u01);
        rx_compose(u00, u01, cosf(0.5f*th), sinf(0.5f*th), v00, v01);
        FGS[f][0] = splat(v00.x);  FGS[f][1] = splat(v01.x);
        FGS[f][2] = splat(v00.y);  FGS[f][3] = splat(v01.y);
        FGS[f][4] = splat(-v00.y); FGS[f][5] = splat(-v01.y);
        FGS[f][6] = splat(-v01.x); FGS[f][7] = 0ull;
    }
    // Zero only the WHT feature columns (28..35).
    {
        const int row = tid >> 3, col = 28 + (tid & 7);
        FW[row][col] = 0ull;
    }
    __syncthreads();

    // ---- P1: S={8,9,10,11} (b0=w3,b1=w2,b2=w1,b3=w0) ----
    {
        v1q_real<3>(R, I, GS[0]);        // 1q w0 (bit11), state real
        c1q<3,2>(R, I, GS[1], FGS[0]);   // 1q w1 + CRX(0,1)
        c1q<2,1>(R, I, GS[2], FGS[1]);   // 1q w2 + CRX(1,2)
        c1q<1,0>(R, I, GS[3], FGS[2]);   // 1q w3 + CRX(2,3)
        vst<8,9,10,11>(R, I, cxp, swzc(tid));
    }
    __syncthreads();

    // ---- P2: S={5,6,7,8}; interleaved load + first gate c1q<3,2>(GS4,FGS3) ----
    // c1q<KC=3,KT=2>: pairs (j, j|4); ctrl = bit3 of j.
    {
        enum { S0 = 5, S1 = 6, S2 = 7, S3 = 8 };
        const int pb = swzc(mkbase<0,1,2,3,4, 9,10,11>(tid));
        {   // ctrl=0 pairs: (0,4),(1,5),(2,6),(3,7)
            LOAD_G7(GS[4])
            LD4(0,4,1,5)     V1Q_BODY(0,4);   V1Q_BODY(1,5);
            LD4(2,6,3,7)     V1Q_BODY(2,6);   V1Q_BODY(3,7);
        }
        {   // ctrl=1 pairs: (8,12),(9,13),(10,14),(11,15)
            LOAD_G7(FGS[3])
            LD4(8,12,9,13)   V1Q_BODY(8,12);  V1Q_BODY(9,13);
            LD4(10,14,11,15) V1Q_BODY(10,14); V1Q_BODY(11,15);
        }
        c1q<2,1>(R, I, GS[5], FGS[4]);   // 1q w5 + CRX(4,5)
        c1q<1,0>(R, I, GS[6], FGS[5]);   // 1q w6 + CRX(5,6)
        vst<5,6,7,8>(R, I, cxp, pb);
    }
    __syncthreads();

    // ---- P3: S={2,3,4,5}; interleaved load + first gate c1q<3,2>(GS7,FGS6) ----
    {
        enum { S0 = 2, S1 = 3, S2 = 4, S3 = 5 };
        const int pb = swzc(mkbase<0,1,7,8,9, 6,10,11>(tid));
        {   // ctrl=0 pairs: (0,4),(1,5),(2,6),(3,7)
            LOAD_G7(GS[7])
            LD4(0,4,1,5)     V1Q_BODY(0,4);   V1Q_BODY(1,5);
            LD4(2,6,3,7)     V1Q_BODY(2,6);   V1Q_BODY(3,7);
        }
        {   // ctrl=1 pairs: (8,12),(9,13),(10,14),(11,15)
            LOAD_G7(FGS[6])
            LD4(8,12,9,13)   V1Q_BODY(8,12);  V1Q_BODY(9,13);
            LD4(10,14,11,15) V1Q_BODY(10,14); V1Q_BODY(11,15);
        }
        c1q<2,1>(R, I, GS[8], FGS[7]);   // 1q w8 + CRX(7,8)
        c1q<1,0>(R, I, GS[9], FGS[8]);   // 1q w9 + CRX(8,9)
        vst<2,3,4,5>(R, I, cxp, pb);
    }
    __syncthreads();

    XY a11, a10;     // deferred from P4
    // ---- P4 (mega): S={0,1,2,11}; interleaved load + first gate c1q<2,1>(GS10,FGS9) ----
    // c1q<KC=2,KT=1>: pairs (j, j|2); ctrl = bit2 of j.
    {
        enum { S0 = 0, S1 = 1, S2 = 2, S3 = 11 };
        const int pb = swzc(mkbase<5,6,7,3,4, 8,9,10>(tid));
        {   // ctrl=0 pairs: (0,2),(1,3),(8,10),(9,11)
            LOAD_G7(GS[10])
            LD4(0,2,1,3)     V1Q_BODY(0,2);   V1Q_BODY(1,3);
            LD4(8,10,9,11)   V1Q_BODY(8,10);  V1Q_BODY(9,11);
        }
        {   // ctrl=1 pairs: (4,6),(5,7),(12,14),(13,15)
            LOAD_G7(FGS[9])
            LD4(4,6,5,7)     V1Q_BODY(4,6);   V1Q_BODY(5,7);
            LD4(12,14,13,15) V1Q_BODY(12,14); V1Q_BODY(13,15);
        }
        c1q<1,0>(R, I, GS[11], FGS[10]); // L0 1q w11 + CRX(10,11)
        vcrx<0,3>(R, I, CC[11]);         // L0 CRX(11,0)
        v1q<0>(R, I, GS[23]);            // L1 1q w11
        v1q<1>(R, I, GS[22]);            // L1 1q w10
        v1q<2>(R, I, GS[21]);            // L1 1q w9
        c1q<0,3>(R, I, GS[12], FGS[11]); // L1 1q w0 + L1 CRX(11,0)
        vcrx<1,0>(R, I, CC[13]);         // L1 CRX(10,11)
        vcrx<2,1>(R, I, CC[14]);         // L1 CRX(9,10)
        vst<0,1,2,11>(R, I, cxp, pb);
        a11 = vcross_acc<0>(R, I);       // idx bit0 -> qubit 11 (final)
        a10 = vcross_acc<1>(R, I);       // idx bit1 -> qubit 10 (final)
    }
    __syncthreads();

    XY a9, a8, a7;   // deferred from P5
    // ---- P5: S={2,3,4,5}; interleaved load + first gate v1q<1>(GS20); fin(P4) after ----
    // v1q<1>: pairs (j, j|2); lo j in {0,1,4,5,8,9,12,13}.
    {
        enum { S0 = 2, S1 = 3, S2 = 4, S3 = 5 };
        const int pb = swzc(mkbase<0,1,7,8,9, 6,10,11>(tid));
        {
            LOAD_G7(GS[20])
            LD4(0,2,1,3)     V1Q_BODY(0,2);   V1Q_BODY(1,3);
            LD4(4,6,5,7)     V1Q_BODY(4,6);   V1Q_BODY(5,7);
            LD4(8,10,9,11)   V1Q_BODY(8,10);  V1Q_BODY(9,11);
            LD4(12,14,13,15) V1Q_BODY(12,14); V1Q_BODY(13,15);
        }
        vcross_fin(a11, fw4, 11);
        vcross_fin(a10, fw4, 10);
        v1q<2>(R, I, GS[19]);
        v1q<3>(R, I, GS[18]);
        vcrx<1,0>(R, I, CC[15]);    // CRX(8,9)
        vcrx<2,1>(R, I, CC[16]);    // CRX(7,8)
        vcrx<3,2>(R, I, CC[17]);    // CRX(6,7)
        vst<2,3,4,5>(R, I, cxp, pb);
        a9 = vcross_acc<0>(R, I);
        a8 = vcross_acc<1>(R, I);
        a7 = vcross_acc<2>(R, I);
    }
    __syncthreads();

    XY a6, a5, a4;   // deferred from P6
    // ---- P6: S={5,6,7,8}; interleaved load + first gate v1q<1>(GS17); fin(P5) after ----
    {
        enum { S0 = 5, S1 = 6, S2 = 7, S3 = 8 };
        const int pb = swzc(mkbase<0,1,2,3,4, 9,10,11>(tid));
        {
            LOAD_G7(GS[17])
            LD4(0,2,1,3)     V1Q_BODY(0,2);   V1Q_BODY(1,3);
            LD4(4,6,5,7)     V1Q_BODY(4,6);   V1Q_BODY(5,7);
            LD4(8,10,9,11)   V1Q_BODY(8,10);  V1Q_BODY(9,11);
            LD4(12,14,13,15) V1Q_BODY(12,14); V1Q_BODY(13,15);
        }
        vcross_fin(a9, fw4, 9);
        vcross_fin(a8, fw4, 8);
        vcross_fin(a7, fw4, 7);
        v1q<2>(R, I, GS[16]);
        v1q<3>(R, I, GS[15]);
        vcrx<1,0>(R, I, CC[18]);    // CRX(5,6)
        vcrx<2,1>(R, I, CC[19]);    // CRX(4,5)
        vcrx<3,2>(R, I, CC[20]);    // CRX(3,4)
        vst<5,6,7,8>(R, I, cxp, pb);
        a6 = vcross_acc<0>(R, I);
        a5 = vcross_acc<1>(R, I);
        a4 = vcross_acc<2>(R, I);
    }
    __syncthreads();

    // ---- P7: S={8,9,10,11}; interleaved load + first gate v1q<1>(GS14); fin(P6) after ----
    {
        enum { S0 = 8, S1 = 9, S2 = 10, S3 = 11 };
        const int pb = swzc(tid);
        {
            LOAD_G7(GS[14])
            LD4(0,2,1,3)     V1Q_BODY(0,2);   V1Q_BODY(1,3);
            LD4(4,6,5,7)     V1Q_BODY(4,6);   V1Q_BODY(5,7);
            LD4(8,10,9,11)   V1Q_BODY(8,10);  V1Q_BODY(9,11);
            LD4(12,14,13,15) V1Q_BODY(12,14); V1Q_BODY(13,15);
        }
        vcross_fin(a6, fw4, 6);
        vcross_fin(a5, fw4, 5);
        vcross_fin(a4, fw4, 4);
        v1q<2>(R, I, GS[13]);       // wire1
        vcrx<1,0>(R, I, CC[21]);    // CRX(2,3)
        vcrx<2,1>(R, I, CC[22]);    // CRX(1,2)
        vcrx<3,2>(R, I, CC[23]);    // CRX(0,1)

        // |amp|^2 sums (packed per batch)
        u64 tot2 = 0ull, d0v = 0ull, d1v = 0ull, d2v = 0ull, d3v = 0ull;
#pragma unroll
        for (int j = 0; j < 16; j++) {
            const u64 p2 = f2fma(R[j], R[j], f2mul(I[j], I[j]));
            tot2 = f2add(tot2, p2);
            if (j & 1) d0v = f2add(d0v, p2);
            if (j & 2) d1v = f2add(d1v, p2);
            if (j & 4) d2v = f2add(d2v, p2);
            if (j & 8) d3v = f2add(d3v, p2);
        }
        // Z for tile bits 8..11 -> qubits 3..0
        red2w4(f2sub(tot2, f2add(d0v, d0v)), fw4, 24 + 3);
        red2w4(f2sub(tot2, f2add(d1v, d1v)), fw4, 24 + 2);
        red2w4(f2sub(tot2, f2add(d2v, d2v)), fw4, 24 + 1);
        red2w4(f2sub(tot2, f2add(d3v, d3v)), fw4, 24 + 0);

        // Z for free bits: 5-stage Walsh-Hadamard butterfly over the warp.
        {
            u64 x = tot2;
#pragma unroll
            for (int m = 1; m <= 16; m <<= 1) {
                const u64 y = __shfl_xor_sync(0xffffffffu, x, m);
                x = (tid & m) ? f2sub(y, x) : f2add(x, y);
            }
            const int lane = tid & 31;
            if (lane == 1)  fw4[24 + 11] = x;   // fb0 -> q11
            if (lane == 2)  fw4[24 + 10] = x;   // fb1 -> q10
            if (lane == 4)  fw4[24 + 9]  = x;   // fb2 -> q9
            if (lane == 8)  fw4[24 + 8]  = x;   // fb3 -> q8
            if (lane == 16) fw4[24 + 7]  = x;   // fb4 -> q7
            if (lane == 0) {
#pragma unroll
                for (int fb = 5; fb < 8; fb++) {   // warp-uniform sign bits -> q6,q5,q4
                    const u64 v = ((tid >> fb) & 1) ? f2sub(0ull, x) : x;
                    fw4[24 + (11 - fb)] = v;
                }
            }
        }

        // X/Y for tile bits 8..11 -> qubits 3..0 (terminal: inline)
        vcross_fin(vcross_acc<0>(R, I), fw4, 3);
        vcross_fin(vcross_acc<1>(R, I), fw4, 2);
        vcross_fin(vcross_acc<2>(R, I), fw4, 1);
        vcross_fin(vcross_acc<3>(R, I), fw4, 0);
    }
    __syncthreads();

    // ---- Parallel reduce: 32 rows -> 8 rows, then 8 -> 1 ----
    if (tid < 8 * NFEAT) {
        const int feat = tid / 8;
        const int grp  = tid % 8;
        const int r0 = grp * 4;
        u64 acc = f2add(f2add(FW[r0][feat], FW[r0+1][feat]),
                        f2add(FW[r0+2][feat], FW[r0+3][feat]));
        FW[r0][feat] = acc;
    }
    __syncthreads();
    if (tid < NFEAT) {
        u64 acc = FW[0][tid];
#pragma unroll
        for (int g = 1; g < 8; g++) acc = f2add(acc, FW[g * 4][tid]);
        FZ[tid] = acc;
    }
    __syncthreads();

    if (tid < 2 * NCLASSES) {
        const int batch = tid / NCLASSES;
        const int c     = tid % NCLASSES;
        const float* fz = (const float*)FZ;     // {b0,b1} interleaved per feature
        float acc = bv[c];
#pragma unroll
        for (int j = 0; j < NFEAT; ++j)
            acc += Wm[c * NFEAT + j] * fz[2 * j + batch];
        out[((size_t)(2 * bidx) + batch) * NCLASSES + c] = acc;
    }
}

extern "C" void kernel_launch(void* const* d_in, const int* in_sizes, int n_in,
                              void* d_out, int out_size)
{
    const float* sv     = (const float*)d_in[0];  // [2048, 4096]
    const float* angles = (const float*)d_in[1];  // [96]
    const float* Wm     = (const float*)d_in[2];  // [10, 36]
    const float* bv     = (const float*)d_in[3];  // [10]
    float* out          = (float*)d_out;          // [2048, 10]
    (void)in_sizes; (void)n_in; (void)out_size;

    const int smem_bytes = DIM * (int)sizeof(longlong2);  // 64 KB dynamic
    cudaFuncSetAttribute(qsim_kernel, cudaFuncAttributeMaxDynamicSharedMemorySize, smem_bytes);
    qsim_kernel<<<1024, THREADS, smem_bytes>>>(sv, angles, Wm, bv, out);
}